// round 15
// baseline (speedup 1.0000x reference)
#include <cuda_runtime.h>
#include <cuda_bf16.h>
#include <math.h>
#include <stdint.h>

#define B_ROWS 8192
#define D_DIM  256
#define JSPLIT 64                        // one 128-col j-tile per split
#define NSPLIT 64
#define NCTA   (64 * JSPLIT)             // 4096 CTAs in lse grid
#define BM 128
#define BN 128
#define BK 64
#define NCHUNK (D_DIM / BK)              // 4 chunks per CTA
#define STAGE_MAT_B (BM * BK * 2)        // 16384 bytes per matrix stage
#define STAGE_B     (2 * STAGE_MAT_B)    // A+B per stage = 32768
#define SMEM_REQ    (3 * STAGE_B + 1024) // 96KB ring + align pad
#define LOG2E 1.4426950408889634f
#define LN2   0.6931471805599453f

// ---- device scratch ----
__device__ __nv_bfloat16 g_predh[B_ROWS * D_DIM];
__device__ __nv_bfloat16 g_targh[B_ROWS * D_DIM];
__device__ float  g_t2l[B_ROWS];                 // 0.5*||t||^2/var * log2e
__device__ float  g_sii[B_ROWS];                 // diagonal, nats
__device__ float  g_l[NSPLIT][B_ROWS];           // raw exp2 sums (no max shift)
__device__ double g_part[32];
__device__ unsigned g_cnt;
__device__ unsigned g_cnt2;

// ---- helpers ----
__device__ __forceinline__ uint32_t smem_u32(const void* p) {
    uint32_t a;
    asm("{ .reg .u64 t; cvta.to.shared.u64 t, %1; cvt.u32.u64 %0, t; }" : "=r"(a) : "l"(p));
    return a;
}
__device__ __forceinline__ float ex2f(float x) {
    float r; asm("ex2.approx.f32 %0, %1;" : "=f"(r) : "f"(x)); return r;
}
__device__ __forceinline__ float lg2f(float x) {
    float r; asm("lg2.approx.f32 %0, %1;" : "=f"(r) : "f"(x)); return r;
}
__device__ __forceinline__ void ldsm4(uint32_t* r, uint32_t addr) {
    asm volatile("ldmatrix.sync.aligned.m8n8.x4.shared.b16 {%0,%1,%2,%3}, [%4];"
                 : "=r"(r[0]), "=r"(r[1]), "=r"(r[2]), "=r"(r[3]) : "r"(addr));
}
__device__ __forceinline__ void mma_bf16(float* d, const uint32_t* a, const uint32_t* b) {
    asm volatile(
        "mma.sync.aligned.m16n8k16.row.col.f32.bf16.bf16.f32 "
        "{%0,%1,%2,%3}, {%4,%5,%6,%7}, {%8,%9}, {%0,%1,%2,%3};"
        : "+f"(d[0]), "+f"(d[1]), "+f"(d[2]), "+f"(d[3])
        : "r"(a[0]), "r"(a[1]), "r"(a[2]), "r"(a[3]), "r"(b[0]), "r"(b[1]));
}
__device__ __forceinline__ void cp16(uint32_t dst, const void* src) {
    asm volatile("cp.async.cg.shared.global [%0], [%1], 16;" :: "r"(dst), "l"(src));
}
#define CP_COMMIT() asm volatile("cp.async.commit_group;" ::: "memory")
#define CP_WAIT(n)  asm volatile("cp.async.wait_group %0;" :: "n"(n) : "memory")

// ---------------------------------------------------------------------------
// Kernel 1: bf16-rounded copies; t2l + s_ii from the ROUNDED values.
// (R13 form — bandwidth-plateau bound; do not touch.)
__global__ void prep_kernel(const float* __restrict__ pred,
                            const float* __restrict__ target,
                            const float* __restrict__ sigma_p) {
    if (blockIdx.x == 0 && threadIdx.x == 0) { g_cnt = 0; g_cnt2 = 0; }
    int row  = blockIdx.x * 8 + (threadIdx.x >> 5);
    int lane = threadIdx.x & 31;
    const float4* t4 = (const float4*)(target + (size_t)row * D_DIM);
    const float4* p4 = (const float4*)(pred   + (size_t)row * D_DIM);
    __nv_bfloat162* ph = (__nv_bfloat162*)(g_predh + (size_t)row * D_DIM);
    __nv_bfloat162* th = (__nv_bfloat162*)(g_targh + (size_t)row * D_DIM);
    float t2 = 0.f, dp = 0.f;
    #pragma unroll
    for (int i = lane; i < D_DIM / 4; i += 32) {
        float4 t = t4[i]; float4 p = p4[i];
        __nv_bfloat162 p0 = __floats2bfloat162_rn(p.x, p.y);
        __nv_bfloat162 p1 = __floats2bfloat162_rn(p.z, p.w);
        __nv_bfloat162 t0 = __floats2bfloat162_rn(t.x, t.y);
        __nv_bfloat162 t1 = __floats2bfloat162_rn(t.z, t.w);
        ph[i * 2] = p0; ph[i * 2 + 1] = p1;
        th[i * 2] = t0; th[i * 2 + 1] = t1;
        float tx = __bfloat162float(t0.x), ty = __bfloat162float(t0.y);
        float tz = __bfloat162float(t1.x), tw = __bfloat162float(t1.y);
        float px = __bfloat162float(p0.x), py = __bfloat162float(p0.y);
        float pz = __bfloat162float(p1.x), pw = __bfloat162float(p1.y);
        t2 += tx*tx + ty*ty + tz*tz + tw*tw;
        dp += px*tx + py*ty + pz*tz + pw*tw;
    }
    #pragma unroll
    for (int o = 16; o > 0; o >>= 1) {
        t2 += __shfl_xor_sync(0xffffffffu, t2, o);
        dp += __shfl_xor_sync(0xffffffffu, dp, o);
    }
    if (lane == 0) {
        float sig = *sigma_p;
        float inv_var = 1.0f / (sig * sig);
        g_t2l[row] = 0.5f * t2 * inv_var * LOG2E;
        g_sii[row] = (dp - 0.5f * t2) * inv_var;
    }
}

// ---------------------------------------------------------------------------
// Kernel 2: bf16 mma GEMM + fused LSE (log2 domain, NO max shift) + in-kernel
// final reduction via deterministic ticket tail (last 32 slots each reduce a
// 256-row slice; slot->rows mapping is fixed, so result is bitwise stable).
__global__ __launch_bounds__(128, 2)
void lse_mma_kernel(const float* __restrict__ sigma_p, float* __restrict__ out) {
    extern __shared__ __align__(16) float dsm[];
    uint32_t raw = smem_u32(dsm);
    uint32_t sb  = (raw + 1023u) & ~1023u;
    char* gb = (char*)dsm + (sb - raw);

    // overlays on ring stage 1 (dead after chunk 1)
    float*    plb  = (float*)(gb + STAGE_B);           // [2][128]
    unsigned* stk  = (unsigned*)(gb + STAGE_B + 1024); // ticket broadcast
    double*   sdd  = (double*)(gb + STAGE_B + 2048);   // [128] tail reduce

    const int tid  = threadIdx.x;
    const int wid  = tid >> 5;
    const int lane = tid & 31;
    const int wr = wid >> 1;
    const int wc = wid & 1;
    const int g  = lane >> 2;
    const int t  = lane & 3;
    const int row0 = blockIdx.x * BM;
    const int col0 = blockIdx.y * BN;

    const float sig = *sigma_p;
    const float invvar2 = (1.0f / (sig * sig)) * LOG2E;

    const int mat = lane >> 3;
    const int lr  = lane & 7;
    const uint32_t rowAoff = (uint32_t)((wr * 64 + (mat & 1) * 8 + lr) * 128);
    const uint32_t rowBoff = (uint32_t)((wc * 64 + (mat >> 1) * 8 + lr) * 128);
    uint32_t colA_sw[4], colB_sw[4];
    #pragma unroll
    for (int ks = 0; ks < 4; ks++) {
        colA_sw[ks] = (uint32_t)(((ks * 2 + (mat >> 1)) << 4) ^ (lr << 4));
        colB_sw[ks] = (uint32_t)(((ks * 2 + (mat & 1)) << 4) ^ (lr << 4));
    }

    uint32_t stA[3], stB[3];
    #pragma unroll
    for (int s = 0; s < 3; s++) {
        stA[s] = sb + s * STAGE_B;
        stB[s] = sb + s * STAGE_B + STAGE_MAT_B;
    }

    int ldr[8], ldc[8];
    uint32_t dst_off[8];
    #pragma unroll
    for (int q = 0; q < 8; q++) {
        int idx = tid + q * 128;
        ldr[q] = idx >> 3;
        ldc[q] = idx & 7;
        uint32_t off = (uint32_t)(ldr[q] * 128 + ldc[q] * 16);
        dst_off[q] = off ^ (((uint32_t)(ldr[q] & 7)) << 4);
    }

    const __nv_bfloat16* pA = g_predh + (size_t)row0 * D_DIM;
    const __nv_bfloat16* pB = g_targh + (size_t)col0 * D_DIM;

    auto issue = [&](int c, uint32_t Au, uint32_t Bu) {
        const __nv_bfloat16* pAc = pA + c * BK;
        const __nv_bfloat16* pBc = pB + c * BK;
        #pragma unroll
        for (int q = 0; q < 8; q++)
            cp16(Au + dst_off[q], pAc + (size_t)ldr[q] * D_DIM + ldc[q] * 8);
        #pragma unroll
        for (int q = 0; q < 8; q++)
            cp16(Bu + dst_off[q], pBc + (size_t)ldr[q] * D_DIM + ldc[q] * 8);
        CP_COMMIT();
    };

    issue(0, stA[0], stB[0]);
    issue(1, stA[1], stB[1]);

    float acc[4][8][4];
    #pragma unroll
    for (int mf = 0; mf < 4; mf++)
        #pragma unroll
        for (int nf = 0; nf < 8; nf++)
            #pragma unroll
            for (int e = 0; e < 4; e++) acc[mf][nf][e] = 0.0f;

    #pragma unroll
    for (int kc = 0; kc < NCHUNK; kc++) {
        if (kc == NCHUNK - 1) { CP_WAIT(0); } else { CP_WAIT(1); }
        __syncthreads();
        if (kc + 2 < NCHUNK) issue(kc + 2, stA[(kc + 2) % 3], stB[(kc + 2) % 3]);

        const uint32_t aB = stA[kc % 3] + rowAoff;
        const uint32_t bB = stB[kc % 3] + rowBoff;
        #pragma unroll
        for (int ks = 0; ks < 4; ks++) {
            uint32_t af[4][4], bf[4][4];
            #pragma unroll
            for (int mf = 0; mf < 4; mf++)
                ldsm4(af[mf], aB + (uint32_t)(mf * 2048) + colA_sw[ks]);
            #pragma unroll
            for (int np = 0; np < 4; np++)
                ldsm4(bf[np], bB + (uint32_t)(np * 2048) + colB_sw[ks]);
            #pragma unroll
            for (int mf = 0; mf < 4; mf++)
                #pragma unroll
                for (int nf = 0; nf < 8; nf++)
                    mma_bf16(acc[mf][nf], af[mf], &bf[nf >> 1][(nf & 1) * 2]);
        }
    }

    // ---- epilogue: direct exp2 sums (no max shift, no rescale) ----
    float tv[16];
    #pragma unroll
    for (int nf = 0; nf < 8; nf++)
        #pragma unroll
        for (int w = 0; w < 2; w++)
            tv[nf * 2 + w] = g_t2l[col0 + wc * 64 + nf * 8 + 2 * t + w];

    #pragma unroll
    for (int mf = 0; mf < 4; mf++) {
        #pragma unroll
        for (int h = 0; h < 2; h++) {
            float sum = 0.0f;
            #pragma unroll
            for (int nf = 0; nf < 8; nf++)
                #pragma unroll
                for (int w = 0; w < 2; w++)
                    sum += ex2f(fmaf(acc[mf][nf][h * 2 + w], invvar2,
                                     -tv[nf * 2 + w]));
            sum += __shfl_xor_sync(0xffffffffu, sum, 1);
            sum += __shfl_xor_sync(0xffffffffu, sum, 2);
            if (t == 0) {
                int rt = wr * 64 + mf * 16 + h * 8 + g;
                plb[wc * BM + rt] = sum;
            }
        }
    }
    __syncthreads();
    g_l[blockIdx.y][row0 + tid] = plb[tid] + plb[BM + tid];

    // ---- ticket tail: last 32 slots do the final reduction ----
    __threadfence();
    if (tid == 0) stk[0] = atomicAdd(&g_cnt, 1u);
    __syncthreads();
    const unsigned ticket = stk[0];
    if (ticket >= (unsigned)(NCTA - 32)) {
        const int slot = (int)(ticket - (NCTA - 32));
        if (tid == 0) {
            volatile unsigned* vc = &g_cnt;
            while (*vc < (unsigned)NCTA) { }
        }
        __syncthreads();
        double accd = 0.0;
        #pragma unroll
        for (int r = 0; r < 2; r++) {
            int i = slot * 256 + r * 128 + tid;
            float l = 0.0f;
            #pragma unroll 16
            for (int s = 0; s < NSPLIT; s++) l += __ldg(&g_l[s][i]);
            accd += (double)(lg2f(l) * LN2 - g_sii[i]);
        }
        sdd[tid] = accd;
        __syncthreads();
        #pragma unroll
        for (int s = 64; s > 0; s >>= 1) {
            if (tid < s) sdd[tid] += sdd[tid + s];
            __syncthreads();
        }
        if (tid == 0) {
            g_part[slot] = sdd[0];
            __threadfence();
            unsigned old = atomicAdd(&g_cnt2, 1u);
            if (old == 31u) {
                double s = 0.0;
                #pragma unroll
                for (int b = 0; b < 32; b++) s += g_part[b];
                double scale = 2.0 * (double)sig * (double)sig / (double)B_ROWS;
                out[0] = (float)(s * scale);
            }
        }
    }
}

// ---------------------------------------------------------------------------
extern "C" void kernel_launch(void* const* d_in, const int* in_sizes, int n_in,
                              void* d_out, int out_size) {
    const float* pred   = (const float*)d_in[0];
    const float* target = (const float*)d_in[1];
    const float* sigma  = (const float*)d_in[2];
    float* out = (float*)d_out;

    cudaFuncSetAttribute(lse_mma_kernel, cudaFuncAttributeMaxDynamicSharedMemorySize, SMEM_REQ);

    prep_kernel<<<B_ROWS / 8, 256>>>(pred, target, sigma);
    lse_mma_kernel<<<dim3(B_ROWS / BM, JSPLIT), 128, SMEM_REQ>>>(sigma, out);
}

// round 16
// speedup vs baseline: 1.0549x; 1.0549x over previous
#include <cuda_runtime.h>
#include <cuda_bf16.h>
#include <math.h>
#include <stdint.h>

#define B_ROWS 8192
#define D_DIM  256
#define JSPLIT 64                        // one 128-col j-tile per split
#define NSPLIT 64
#define BM 128
#define BN 128
#define BK 64
#define NCHUNK (D_DIM / BK)              // 4 chunks per CTA
#define STAGE_MAT_B (BM * BK * 2)        // 16384 bytes per matrix stage
#define STAGE_B     (2 * STAGE_MAT_B)    // A+B per stage = 32768
#define SMEM_REQ    (3 * STAGE_B + 1024) // 96KB ring + align pad
#define LOG2E 1.4426950408889634f
#define LN2   0.6931471805599453f

// ---- device scratch ----
__device__ __nv_bfloat16 g_predh[B_ROWS * D_DIM];
__device__ __nv_bfloat16 g_targh[B_ROWS * D_DIM];
__device__ float  g_t2l[B_ROWS];                 // 0.5*||t||^2/var * log2e
__device__ float  g_sii[B_ROWS];                 // diagonal, nats
__device__ float  g_l[NSPLIT][B_ROWS];           // raw exp2 sums (no max shift)
__device__ double g_part[32];
__device__ unsigned g_cnt;

// ---- helpers ----
__device__ __forceinline__ uint32_t smem_u32(const void* p) {
    uint32_t a;
    asm("{ .reg .u64 t; cvta.to.shared.u64 t, %1; cvt.u32.u64 %0, t; }" : "=r"(a) : "l"(p));
    return a;
}
__device__ __forceinline__ float ex2f(float x) {
    float r; asm("ex2.approx.f32 %0, %1;" : "=f"(r) : "f"(x)); return r;
}
__device__ __forceinline__ float lg2f(float x) {
    float r; asm("lg2.approx.f32 %0, %1;" : "=f"(r) : "f"(x)); return r;
}
__device__ __forceinline__ void ldsm4(uint32_t* r, uint32_t addr) {
    asm volatile("ldmatrix.sync.aligned.m8n8.x4.shared.b16 {%0,%1,%2,%3}, [%4];"
                 : "=r"(r[0]), "=r"(r[1]), "=r"(r[2]), "=r"(r[3]) : "r"(addr));
}
__device__ __forceinline__ void mma_bf16(float* d, const uint32_t* a, const uint32_t* b) {
    asm volatile(
        "mma.sync.aligned.m16n8k16.row.col.f32.bf16.bf16.f32 "
        "{%0,%1,%2,%3}, {%4,%5,%6,%7}, {%8,%9}, {%0,%1,%2,%3};"
        : "+f"(d[0]), "+f"(d[1]), "+f"(d[2]), "+f"(d[3])
        : "r"(a[0]), "r"(a[1]), "r"(a[2]), "r"(a[3]), "r"(b[0]), "r"(b[1]));
}
__device__ __forceinline__ void cp16(uint32_t dst, const void* src) {
    asm volatile("cp.async.cg.shared.global [%0], [%1], 16;" :: "r"(dst), "l"(src));
}
#define CP_COMMIT() asm volatile("cp.async.commit_group;" ::: "memory")
#define CP_WAIT(n)  asm volatile("cp.async.wait_group %0;" :: "n"(n) : "memory")

// ---------------------------------------------------------------------------
// Kernel 1: bf16-rounded copies; t2l + s_ii from the ROUNDED values.
__global__ void prep_kernel(const float* __restrict__ pred,
                            const float* __restrict__ target,
                            const float* __restrict__ sigma_p) {
    if (blockIdx.x == 0 && threadIdx.x == 0) g_cnt = 0;
    int row  = blockIdx.x * 8 + (threadIdx.x >> 5);
    int lane = threadIdx.x & 31;
    const float4* t4 = (const float4*)(target + (size_t)row * D_DIM);
    const float4* p4 = (const float4*)(pred   + (size_t)row * D_DIM);
    __nv_bfloat162* ph = (__nv_bfloat162*)(g_predh + (size_t)row * D_DIM);
    __nv_bfloat162* th = (__nv_bfloat162*)(g_targh + (size_t)row * D_DIM);
    float t2 = 0.f, dp = 0.f;
    #pragma unroll
    for (int i = lane; i < D_DIM / 4; i += 32) {
        float4 t = t4[i]; float4 p = p4[i];
        __nv_bfloat162 p0 = __floats2bfloat162_rn(p.x, p.y);
        __nv_bfloat162 p1 = __floats2bfloat162_rn(p.z, p.w);
        __nv_bfloat162 t0 = __floats2bfloat162_rn(t.x, t.y);
        __nv_bfloat162 t1 = __floats2bfloat162_rn(t.z, t.w);
        ph[i * 2] = p0; ph[i * 2 + 1] = p1;
        th[i * 2] = t0; th[i * 2 + 1] = t1;
        float tx = __bfloat162float(t0.x), ty = __bfloat162float(t0.y);
        float tz = __bfloat162float(t1.x), tw = __bfloat162float(t1.y);
        float px = __bfloat162float(p0.x), py = __bfloat162float(p0.y);
        float pz = __bfloat162float(p1.x), pw = __bfloat162float(p1.y);
        t2 += tx*tx + ty*ty + tz*tz + tw*tw;
        dp += px*tx + py*ty + pz*tz + pw*tw;
    }
    #pragma unroll
    for (int o = 16; o > 0; o >>= 1) {
        t2 += __shfl_xor_sync(0xffffffffu, t2, o);
        dp += __shfl_xor_sync(0xffffffffu, dp, o);
    }
    if (lane == 0) {
        float sig = *sigma_p;
        float inv_var = 1.0f / (sig * sig);
        g_t2l[row] = 0.5f * t2 * inv_var * LOG2E;
        g_sii[row] = (dp - 0.5f * t2) * inv_var;
    }
}

// ---------------------------------------------------------------------------
// Kernel 2: bf16 mma GEMM + fused LSE (log2 domain, NO max shift).
// Grid (64, 64). A+B 3-stage cp.async ring, 2 CTAs/SM. (R13 champion + 4-way
// partial sums in the epilogue to break the MUFU->FADD chain.)
__global__ __launch_bounds__(128, 2)
void lse_mma_kernel(const float* __restrict__ sigma_p) {
    extern __shared__ __align__(16) float dsm[];
    uint32_t raw = smem_u32(dsm);
    uint32_t sb  = (raw + 1023u) & ~1023u;
    char* gb = (char*)dsm + (sb - raw);

    // half-merge overlay on ring stage 1 (dead after chunk 1)
    float* plb = (float*)(gb + STAGE_B);          // [2][128]

    const int tid  = threadIdx.x;
    const int wid  = tid >> 5;
    const int lane = tid & 31;
    const int wr = wid >> 1;
    const int wc = wid & 1;
    const int g  = lane >> 2;
    const int t  = lane & 3;
    const int row0 = blockIdx.x * BM;
    const int col0 = blockIdx.y * BN;

    const float sig = *sigma_p;
    const float invvar2 = (1.0f / (sig * sig)) * LOG2E;

    const int mat = lane >> 3;
    const int lr  = lane & 7;
    const uint32_t rowAoff = (uint32_t)((wr * 64 + (mat & 1) * 8 + lr) * 128);
    const uint32_t rowBoff = (uint32_t)((wc * 64 + (mat >> 1) * 8 + lr) * 128);
    uint32_t colA_sw[4], colB_sw[4];
    #pragma unroll
    for (int ks = 0; ks < 4; ks++) {
        colA_sw[ks] = (uint32_t)(((ks * 2 + (mat >> 1)) << 4) ^ (lr << 4));
        colB_sw[ks] = (uint32_t)(((ks * 2 + (mat & 1)) << 4) ^ (lr << 4));
    }

    uint32_t stA[3], stB[3];
    #pragma unroll
    for (int s = 0; s < 3; s++) {
        stA[s] = sb + s * STAGE_B;
        stB[s] = sb + s * STAGE_B + STAGE_MAT_B;
    }

    int ldr[8], ldc[8];
    uint32_t dst_off[8];
    #pragma unroll
    for (int q = 0; q < 8; q++) {
        int idx = tid + q * 128;
        ldr[q] = idx >> 3;
        ldc[q] = idx & 7;
        uint32_t off = (uint32_t)(ldr[q] * 128 + ldc[q] * 16);
        dst_off[q] = off ^ (((uint32_t)(ldr[q] & 7)) << 4);
    }

    const __nv_bfloat16* pA = g_predh + (size_t)row0 * D_DIM;
    const __nv_bfloat16* pB = g_targh + (size_t)col0 * D_DIM;

    auto issue = [&](int c, uint32_t Au, uint32_t Bu) {
        const __nv_bfloat16* pAc = pA + c * BK;
        const __nv_bfloat16* pBc = pB + c * BK;
        #pragma unroll
        for (int q = 0; q < 8; q++)
            cp16(Au + dst_off[q], pAc + (size_t)ldr[q] * D_DIM + ldc[q] * 8);
        #pragma unroll
        for (int q = 0; q < 8; q++)
            cp16(Bu + dst_off[q], pBc + (size_t)ldr[q] * D_DIM + ldc[q] * 8);
        CP_COMMIT();
    };

    issue(0, stA[0], stB[0]);
    issue(1, stA[1], stB[1]);

    float acc[4][8][4];
    #pragma unroll
    for (int mf = 0; mf < 4; mf++)
        #pragma unroll
        for (int nf = 0; nf < 8; nf++)
            #pragma unroll
            for (int e = 0; e < 4; e++) acc[mf][nf][e] = 0.0f;

    #pragma unroll
    for (int kc = 0; kc < NCHUNK; kc++) {
        if (kc == NCHUNK - 1) { CP_WAIT(0); } else { CP_WAIT(1); }
        __syncthreads();
        if (kc + 2 < NCHUNK) issue(kc + 2, stA[(kc + 2) % 3], stB[(kc + 2) % 3]);

        const uint32_t aB = stA[kc % 3] + rowAoff;
        const uint32_t bB = stB[kc % 3] + rowBoff;
        #pragma unroll
        for (int ks = 0; ks < 4; ks++) {
            uint32_t af[4][4], bf[4][4];
            #pragma unroll
            for (int mf = 0; mf < 4; mf++)
                ldsm4(af[mf], aB + (uint32_t)(mf * 2048) + colA_sw[ks]);
            #pragma unroll
            for (int np = 0; np < 4; np++)
                ldsm4(bf[np], bB + (uint32_t)(np * 2048) + colB_sw[ks]);
            #pragma unroll
            for (int mf = 0; mf < 4; mf++)
                #pragma unroll
                for (int nf = 0; nf < 8; nf++)
                    mma_bf16(acc[mf][nf], af[mf], &bf[nf >> 1][(nf & 1) * 2]);
        }
    }

    // ---- epilogue: direct exp2 sums, 4-way partial accumulation ----
    float tv[16];
    #pragma unroll
    for (int nf = 0; nf < 8; nf++)
        #pragma unroll
        for (int w = 0; w < 2; w++)
            tv[nf * 2 + w] = g_t2l[col0 + wc * 64 + nf * 8 + 2 * t + w];

    #pragma unroll
    for (int mf = 0; mf < 4; mf++) {
        #pragma unroll
        for (int h = 0; h < 2; h++) {
            float s0 = 0.f, s1 = 0.f, s2 = 0.f, s3 = 0.f;
            #pragma unroll
            for (int nf = 0; nf < 8; nf += 4) {
                s0 += ex2f(fmaf(acc[mf][nf + 0][h * 2 + 0], invvar2, -tv[nf * 2 + 0]));
                s1 += ex2f(fmaf(acc[mf][nf + 0][h * 2 + 1], invvar2, -tv[nf * 2 + 1]));
                s2 += ex2f(fmaf(acc[mf][nf + 1][h * 2 + 0], invvar2, -tv[nf * 2 + 2]));
                s3 += ex2f(fmaf(acc[mf][nf + 1][h * 2 + 1], invvar2, -tv[nf * 2 + 3]));
                s0 += ex2f(fmaf(acc[mf][nf + 2][h * 2 + 0], invvar2, -tv[nf * 2 + 4]));
                s1 += ex2f(fmaf(acc[mf][nf + 2][h * 2 + 1], invvar2, -tv[nf * 2 + 5]));
                s2 += ex2f(fmaf(acc[mf][nf + 3][h * 2 + 0], invvar2, -tv[nf * 2 + 6]));
                s3 += ex2f(fmaf(acc[mf][nf + 3][h * 2 + 1], invvar2, -tv[nf * 2 + 7]));
            }
            float sum = (s0 + s1) + (s2 + s3);
            sum += __shfl_xor_sync(0xffffffffu, sum, 1);
            sum += __shfl_xor_sync(0xffffffffu, sum, 2);
            if (t == 0) {
                int rt = wr * 64 + mf * 16 + h * 8 + g;
                plb[wc * BM + rt] = sum;
            }
        }
    }
    __syncthreads();
    g_l[blockIdx.y][row0 + tid] = plb[tid] + plb[BM + tid];
}

// ---------------------------------------------------------------------------
// Kernel 3: fixed-order sum of 64 raw split sums per row, one lg2 per row,
// deterministic block+final reduce.
__global__ void reduce_kernel(const float* __restrict__ sigma_p,
                              float* __restrict__ out) {
    __shared__ double sdata[256];
    int i = blockIdx.x * 256 + threadIdx.x;
    double acc;
    {
        float l = 0.0f;
        #pragma unroll 16
        for (int s = 0; s < NSPLIT; s++) l += __ldg(&g_l[s][i]);
        float lse = lg2f(l) * LN2;
        acc = (double)(lse - g_sii[i]);
    }
    sdata[threadIdx.x] = acc;
    __syncthreads();
    #pragma unroll
    for (int s = 128; s > 0; s >>= 1) {
        if (threadIdx.x < s) sdata[threadIdx.x] += sdata[threadIdx.x + s];
        __syncthreads();
    }
    if (threadIdx.x == 0) {
        g_part[blockIdx.x] = sdata[0];
        __threadfence();
        unsigned old = atomicAdd(&g_cnt, 1u);
        if (old == 31u) {
            double s = 0.0;
            #pragma unroll
            for (int b = 0; b < 32; b++) s += g_part[b];
            float sig = *sigma_p;
            double scale = 2.0 * (double)sig * (double)sig / (double)B_ROWS;
            out[0] = (float)(s * scale);
        }
    }
}

// ---------------------------------------------------------------------------
extern "C" void kernel_launch(void* const* d_in, const int* in_sizes, int n_in,
                              void* d_out, int out_size) {
    const float* pred   = (const float*)d_in[0];
    const float* target = (const float*)d_in[1];
    const float* sigma  = (const float*)d_in[2];
    float* out = (float*)d_out;

    cudaFuncSetAttribute(lse_mma_kernel, cudaFuncAttributeMaxDynamicSharedMemorySize, SMEM_REQ);

    prep_kernel<<<B_ROWS / 8, 256>>>(pred, target, sigma);
    lse_mma_kernel<<<dim3(B_ROWS / BM, JSPLIT), 128, SMEM_REQ>>>(sigma);
    reduce_kernel<<<32, 256>>>(sigma, out);
}

// round 17
// speedup vs baseline: 1.1290x; 1.0703x over previous
#include <cuda_runtime.h>
#include <cuda_bf16.h>
#include <math.h>
#include <stdint.h>

#define B_ROWS 8192
#define D_DIM  256
#define JSPLIT 64                        // one 128-col j-tile per split
#define NSPLIT 64
#define BM 128
#define BN 128
#define BK 64
#define NCHUNK (D_DIM / BK)              // 4 chunks per CTA
#define STAGE_MAT_B (BM * BK * 2)        // 16384 bytes per matrix stage
#define STAGE_B     (2 * STAGE_MAT_B)    // A+B per stage = 32768
#define SMEM_REQ    (3 * STAGE_B + 1024) // 96KB ring + align pad
#define LOG2E 1.4426950408889634f
#define LN2   0.6931471805599453f

// ---- device scratch ----
__device__ __nv_bfloat16 g_predh[B_ROWS * D_DIM];
__device__ __nv_bfloat16 g_targh[B_ROWS * D_DIM];
__device__ float  g_t2l[B_ROWS];                 // 0.5*||t||^2/var * log2e
__device__ float  g_sii[B_ROWS];                 // diagonal, nats
__device__ float  g_l[NSPLIT][B_ROWS];           // raw exp2 sums (no max shift)
__device__ double g_part[32];
__device__ unsigned g_cnt;

// ---- helpers ----
__device__ __forceinline__ uint32_t smem_u32(const void* p) {
    uint32_t a;
    asm("{ .reg .u64 t; cvta.to.shared.u64 t, %1; cvt.u32.u64 %0, t; }" : "=r"(a) : "l"(p));
    return a;
}
__device__ __forceinline__ float ex2f(float x) {
    float r; asm("ex2.approx.f32 %0, %1;" : "=f"(r) : "f"(x)); return r;
}
__device__ __forceinline__ float lg2f(float x) {
    float r; asm("lg2.approx.f32 %0, %1;" : "=f"(r) : "f"(x)); return r;
}
__device__ __forceinline__ void ldsm4(uint32_t* r, uint32_t addr) {
    asm volatile("ldmatrix.sync.aligned.m8n8.x4.shared.b16 {%0,%1,%2,%3}, [%4];"
                 : "=r"(r[0]), "=r"(r[1]), "=r"(r[2]), "=r"(r[3]) : "r"(addr));
}
__device__ __forceinline__ void mma_bf16(float* d, const uint32_t* a, const uint32_t* b) {
    asm volatile(
        "mma.sync.aligned.m16n8k16.row.col.f32.bf16.bf16.f32 "
        "{%0,%1,%2,%3}, {%4,%5,%6,%7}, {%8,%9}, {%0,%1,%2,%3};"
        : "+f"(d[0]), "+f"(d[1]), "+f"(d[2]), "+f"(d[3])
        : "r"(a[0]), "r"(a[1]), "r"(a[2]), "r"(a[3]), "r"(b[0]), "r"(b[1]));
}
__device__ __forceinline__ void cp16(uint32_t dst, const void* src) {
    asm volatile("cp.async.cg.shared.global [%0], [%1], 16;" :: "r"(dst), "l"(src));
}
#define CP_COMMIT() asm volatile("cp.async.commit_group;" ::: "memory")
#define CP_WAIT(n)  asm volatile("cp.async.wait_group %0;" :: "n"(n) : "memory")

// ---------------------------------------------------------------------------
// Kernel 1: bf16-rounded copies (packed 8B stores); t2l + s_ii from the
// ROUNDED values.
__global__ void prep_kernel(const float* __restrict__ pred,
                            const float* __restrict__ target,
                            const float* __restrict__ sigma_p) {
    if (blockIdx.x == 0 && threadIdx.x == 0) g_cnt = 0;
    int row  = blockIdx.x * 8 + (threadIdx.x >> 5);
    int lane = threadIdx.x & 31;
    const float4* t4 = (const float4*)(target + (size_t)row * D_DIM);
    const float4* p4 = (const float4*)(pred   + (size_t)row * D_DIM);
    uint2* ph = (uint2*)(g_predh + (size_t)row * D_DIM);
    uint2* th = (uint2*)(g_targh + (size_t)row * D_DIM);
    float t2 = 0.f, dp = 0.f;
    #pragma unroll
    for (int i = lane; i < D_DIM / 4; i += 32) {
        float4 t = t4[i]; float4 p = p4[i];
        __nv_bfloat162 p0 = __floats2bfloat162_rn(p.x, p.y);
        __nv_bfloat162 p1 = __floats2bfloat162_rn(p.z, p.w);
        __nv_bfloat162 t0 = __floats2bfloat162_rn(t.x, t.y);
        __nv_bfloat162 t1 = __floats2bfloat162_rn(t.z, t.w);
        uint2 pu, tu;
        pu.x = *(uint32_t*)&p0; pu.y = *(uint32_t*)&p1;
        tu.x = *(uint32_t*)&t0; tu.y = *(uint32_t*)&t1;
        ph[i] = pu; th[i] = tu;
        float tx = __bfloat162float(t0.x), ty = __bfloat162float(t0.y);
        float tz = __bfloat162float(t1.x), tw = __bfloat162float(t1.y);
        float px = __bfloat162float(p0.x), py = __bfloat162float(p0.y);
        float pz = __bfloat162float(p1.x), pw = __bfloat162float(p1.y);
        t2 += tx*tx + ty*ty + tz*tz + tw*tw;
        dp += px*tx + py*ty + pz*tz + pw*tw;
    }
    #pragma unroll
    for (int o = 16; o > 0; o >>= 1) {
        t2 += __shfl_xor_sync(0xffffffffu, t2, o);
        dp += __shfl_xor_sync(0xffffffffu, dp, o);
    }
    if (lane == 0) {
        float sig = *sigma_p;
        float inv_var = 1.0f / (sig * sig);
        g_t2l[row] = 0.5f * t2 * inv_var * LOG2E;
        g_sii[row] = (dp - 0.5f * t2) * inv_var;
    }
}

// ---------------------------------------------------------------------------
// Kernel 2: bf16 mma GEMM + fused LSE (log2 domain, NO max shift).
// Grid (64, 64). A+B 3-stage cp.async ring, 2 CTAs/SM. (R13 champion, exact.)
__global__ __launch_bounds__(128, 2)
void lse_mma_kernel(const float* __restrict__ sigma_p) {
    extern __shared__ __align__(16) float dsm[];
    uint32_t raw = smem_u32(dsm);
    uint32_t sb  = (raw + 1023u) & ~1023u;
    char* gb = (char*)dsm + (sb - raw);

    // half-merge overlay on ring stage 1 (dead after chunk 1)
    float* plb = (float*)(gb + STAGE_B);          // [2][128]

    const int tid  = threadIdx.x;
    const int wid  = tid >> 5;
    const int lane = tid & 31;
    const int wr = wid >> 1;
    const int wc = wid & 1;
    const int g  = lane >> 2;
    const int t  = lane & 3;
    const int row0 = blockIdx.x * BM;
    const int col0 = blockIdx.y * BN;

    const float sig = *sigma_p;
    const float invvar2 = (1.0f / (sig * sig)) * LOG2E;

    const int mat = lane >> 3;
    const int lr  = lane & 7;
    const uint32_t rowAoff = (uint32_t)((wr * 64 + (mat & 1) * 8 + lr) * 128);
    const uint32_t rowBoff = (uint32_t)((wc * 64 + (mat >> 1) * 8 + lr) * 128);
    uint32_t colA_sw[4], colB_sw[4];
    #pragma unroll
    for (int ks = 0; ks < 4; ks++) {
        colA_sw[ks] = (uint32_t)(((ks * 2 + (mat >> 1)) << 4) ^ (lr << 4));
        colB_sw[ks] = (uint32_t)(((ks * 2 + (mat & 1)) << 4) ^ (lr << 4));
    }

    uint32_t stA[3], stB[3];
    #pragma unroll
    for (int s = 0; s < 3; s++) {
        stA[s] = sb + s * STAGE_B;
        stB[s] = sb + s * STAGE_B + STAGE_MAT_B;
    }

    int ldr[8], ldc[8];
    uint32_t dst_off[8];
    #pragma unroll
    for (int q = 0; q < 8; q++) {
        int idx = tid + q * 128;
        ldr[q] = idx >> 3;
        ldc[q] = idx & 7;
        uint32_t off = (uint32_t)(ldr[q] * 128 + ldc[q] * 16);
        dst_off[q] = off ^ (((uint32_t)(ldr[q] & 7)) << 4);
    }

    const __nv_bfloat16* pA = g_predh + (size_t)row0 * D_DIM;
    const __nv_bfloat16* pB = g_targh + (size_t)col0 * D_DIM;

    auto issue = [&](int c, uint32_t Au, uint32_t Bu) {
        const __nv_bfloat16* pAc = pA + c * BK;
        const __nv_bfloat16* pBc = pB + c * BK;
        #pragma unroll
        for (int q = 0; q < 8; q++)
            cp16(Au + dst_off[q], pAc + (size_t)ldr[q] * D_DIM + ldc[q] * 8);
        #pragma unroll
        for (int q = 0; q < 8; q++)
            cp16(Bu + dst_off[q], pBc + (size_t)ldr[q] * D_DIM + ldc[q] * 8);
        CP_COMMIT();
    };

    issue(0, stA[0], stB[0]);
    issue(1, stA[1], stB[1]);

    float acc[4][8][4];
    #pragma unroll
    for (int mf = 0; mf < 4; mf++)
        #pragma unroll
        for (int nf = 0; nf < 8; nf++)
            #pragma unroll
            for (int e = 0; e < 4; e++) acc[mf][nf][e] = 0.0f;

    #pragma unroll
    for (int kc = 0; kc < NCHUNK; kc++) {
        if (kc == NCHUNK - 1) { CP_WAIT(0); } else { CP_WAIT(1); }
        __syncthreads();
        if (kc + 2 < NCHUNK) issue(kc + 2, stA[(kc + 2) % 3], stB[(kc + 2) % 3]);

        const uint32_t aB = stA[kc % 3] + rowAoff;
        const uint32_t bB = stB[kc % 3] + rowBoff;
        #pragma unroll
        for (int ks = 0; ks < 4; ks++) {
            uint32_t af[4][4], bf[4][4];
            #pragma unroll
            for (int mf = 0; mf < 4; mf++)
                ldsm4(af[mf], aB + (uint32_t)(mf * 2048) + colA_sw[ks]);
            #pragma unroll
            for (int np = 0; np < 4; np++)
                ldsm4(bf[np], bB + (uint32_t)(np * 2048) + colB_sw[ks]);
            #pragma unroll
            for (int mf = 0; mf < 4; mf++)
                #pragma unroll
                for (int nf = 0; nf < 8; nf++)
                    mma_bf16(acc[mf][nf], af[mf], &bf[nf >> 1][(nf & 1) * 2]);
        }
    }

    // ---- epilogue: direct exp2 sums (no max shift, no rescale) ----
    float tv[16];
    #pragma unroll
    for (int nf = 0; nf < 8; nf++)
        #pragma unroll
        for (int w = 0; w < 2; w++)
            tv[nf * 2 + w] = g_t2l[col0 + wc * 64 + nf * 8 + 2 * t + w];

    #pragma unroll
    for (int mf = 0; mf < 4; mf++) {
        #pragma unroll
        for (int h = 0; h < 2; h++) {
            float sum = 0.0f;
            #pragma unroll
            for (int nf = 0; nf < 8; nf++)
                #pragma unroll
                for (int w = 0; w < 2; w++)
                    sum += ex2f(fmaf(acc[mf][nf][h * 2 + w], invvar2,
                                     -tv[nf * 2 + w]));
            sum += __shfl_xor_sync(0xffffffffu, sum, 1);
            sum += __shfl_xor_sync(0xffffffffu, sum, 2);
            if (t == 0) {
                int rt = wr * 64 + mf * 16 + h * 8 + g;
                plb[wc * BM + rt] = sum;
            }
        }
    }
    __syncthreads();
    g_l[blockIdx.y][row0 + tid] = plb[tid] + plb[BM + tid];
}

// ---------------------------------------------------------------------------
// Kernel 3: fixed-order sum of 64 raw split sums per row, one lg2 per row,
// deterministic block+final reduce.
__global__ void reduce_kernel(const float* __restrict__ sigma_p,
                              float* __restrict__ out) {
    __shared__ double sdata[256];
    int i = blockIdx.x * 256 + threadIdx.x;
    double acc;
    {
        float l = 0.0f;
        #pragma unroll 16
        for (int s = 0; s < NSPLIT; s++) l += __ldg(&g_l[s][i]);
        float lse = lg2f(l) * LN2;
        acc = (double)(lse - g_sii[i]);
    }
    sdata[threadIdx.x] = acc;
    __syncthreads();
    #pragma unroll
    for (int s = 128; s > 0; s >>= 1) {
        if (threadIdx.x < s) sdata[threadIdx.x] += sdata[threadIdx.x + s];
        __syncthreads();
    }
    if (threadIdx.x == 0) {
        g_part[blockIdx.x] = sdata[0];
        __threadfence();
        unsigned old = atomicAdd(&g_cnt, 1u);
        if (old == 31u) {
            double s = 0.0;
            #pragma unroll
            for (int b = 0; b < 32; b++) s += g_part[b];
            float sig = *sigma_p;
            double scale = 2.0 * (double)sig * (double)sig / (double)B_ROWS;
            out[0] = (float)(s * scale);
        }
    }
}

// ---------------------------------------------------------------------------
extern "C" void kernel_launch(void* const* d_in, const int* in_sizes, int n_in,
                              void* d_out, int out_size) {
    const float* pred   = (const float*)d_in[0];
    const float* target = (const float*)d_in[1];
    const float* sigma  = (const float*)d_in[2];
    float* out = (float*)d_out;

    cudaFuncSetAttribute(lse_mma_kernel, cudaFuncAttributeMaxDynamicSharedMemorySize, SMEM_REQ);

    prep_kernel<<<B_ROWS / 8, 256>>>(pred, target, sigma);
    lse_mma_kernel<<<dim3(B_ROWS / BM, JSPLIT), 128, SMEM_REQ>>>(sigma);
    reduce_kernel<<<32, 256>>>(sigma, out);
}